// round 9
// baseline (speedup 1.0000x reference)
#include <cuda_runtime.h>

#define NLAT_I 240
#define NLON_I 480
#define NLAT_O 361
#define NLON_O 720
#define CI     32
#define CO     32
#define KK     7
#define WOFF   10

#define PI_F      3.14159265358979323846f
#define TWO_PI_F  6.28318530717958647692f
#define CUTOFF_F  0.08508480103472356f
#define DR_F      0.028361600344907855f
#define DPH_F     2.0943951023931953f

#define XROW 1504   // duplicated longitude row (720*2 + 64)

typedef unsigned long long u64;

// ---------------- device scratch ----------------
static __device__ float g_xud[8 * 361 * XROW * 4];                 // [g][t][q] float4, q = p mod 720 duplicated
static __device__ float g_psi8[(size_t)361 * 21 * 728 * 8];        // [t][d][s][8] = k0..k6, pad
static __device__ float g_sp[7 * 361 * 21];
static __device__ float g_invsc[7 * 361];
static __device__ float g_invs2[361 * 8];                          // (i0..i6, 0) per t
static __device__ float g_w2[32 * 112 * 2];                        // packed weight pairs
static __device__ int   g_m[361 * 21];
static __device__ int   g_m2[361 * 21];

// ---------------- kernel A: bilinear upsample (writes duplicated rows) ----------------
__global__ void upsample_kernel(const float* __restrict__ x) {
    int idx = blockIdx.x * 256 + threadIdx.x;
    if (idx >= CI * NLAT_O * NLON_O) return;
    int p  = idx % NLON_O;
    int tt = (idx / NLON_O) % NLAT_O;
    int i  = idx / (NLON_O * NLAT_O);

    float theta = (float)tt * (PI_F / 360.0f);
    float post  = theta / (PI_F / 239.0f);
    float fi0 = floorf(post);
    int i0 = (int)fi0; i0 = min(max(i0, 0), NLAT_I - 1);
    int i1 = min(i0 + 1, NLAT_I - 1);
    float wt = post - (float)i0;

    float posp = ((float)p * (TWO_PI_F / (float)NLON_O)) / (TWO_PI_F / (float)NLON_I);
    float fj0 = floorf(posp);
    int j0 = ((int)fj0) % NLON_I;
    int j1 = j0 + 1; if (j1 >= NLON_I) j1 = 0;
    float wp = posp - fj0;

    const float* xi = x + i * (NLAT_I * NLON_I);
    float a  = xi[i0 * NLON_I + j0];
    float b  = xi[i0 * NLON_I + j1];
    float c  = xi[i1 * NLON_I + j0];
    float dv = xi[i1 * NLON_I + j1];
    float xl0 = (1.0f - wt) * a + wt * c;
    float xl1 = (1.0f - wt) * b + wt * dv;
    float val = (1.0f - wp) * xl0 + wp * xl1;

    size_t rowb = ((size_t)(i >> 2) * NLAT_O + tt) * XROW;
    int c4 = i & 3;
    g_xud[(rowb + p) * 4 + c4] = val;
    g_xud[(rowb + p + 720) * 4 + c4] = val;
    if (p < 64) g_xud[(rowb + p + 1440) * 4 + c4] = val;
}

// ---------------- kernel B: build psi (slots k0..k6) + bounds ----------------
__global__ void build_psi_kernel() {
    int d = blockIdx.x;
    int t = blockIdx.y;
    int tid = threadIdx.x;

    int lt = t + d - WOFF;
    bool valid = (lt >= 0) && (lt <= NLAT_O - 1);
    int ltc = min(max(lt, 0), NLAT_O - 1);

    float tht = (float)t   * (PI_F / 360.0f);
    float thi = (float)ltc * (PI_F / 360.0f);
    float ca = cosf(tht), sa = sinf(tht);
    float cg = cosf(thi), sg = sinf(thi);
    float A = ca * cg;
    float B = sa * sg;
    float cosc = cosf(CUTOFF_F);

    int m;
    if (!valid)                 m = -1;
    else if (A - B >= cosc)     m = 360;
    else if (A + B <  cosc)     m = -1;
    else {
        float ratio = (cosc - A) / fmaxf(B, 1e-30f);
        ratio = fminf(fmaxf(ratio, -1.0f), 1.0f);
        m = (int)floorf(acosf(ratio) * (360.0f / PI_F)) + 2;
        if (m > 360) m = 360;
    }

    float cosc2i = cosf(2.0f * DR_F);
    float cosc2o = cosf(2.0f * DR_F + 1e-4f);
    int m2;
    if (m < 0)                   m2 = -1;
    else if (A - B >= cosc2i)    m2 = 360;
    else if (A + B <  cosc2o)    m2 = -1;
    else {
        float ratio = (cosc2o - A) / fmaxf(B, 1e-30f);
        ratio = fminf(fmaxf(ratio, -1.0f), 1.0f);
        m2 = (int)floorf(acosf(ratio) * (360.0f / PI_F)) + 3;
        if (m2 > 360) m2 = 360;
    }
    if (tid == 0) { g_m[t * 21 + d] = m; g_m2[t * 21 + d] = m2; }

    float dth = (float)(ltc - t) * (PI_F / 360.0f);
    float shd = sinf(0.5f * dth);
    float hav_lat = shd * shd;

    float sums[7] = {0.f, 0.f, 0.f, 0.f, 0.f, 0.f, 0.f};
    if (m >= 0) {
        float qfac = sg * (PI_F / 360.0f) * (PI_F / 360.0f);
        int cnt = 2 * m + 1;
        for (int s = tid; s < cnt; s += 256) {
            int pp = s - m; if (pp < 0) pp += NLON_O;
            float beta = (float)pp * (TWO_PI_F / (float)NLON_O);
            float cb = cosf(beta), sb = sinf(beta);
            float z = A + cb * B;
            z = fminf(fmaxf(z, -1.0f), 1.0f);
            float r_acos = acosf(z);
            float mask = (r_acos <= CUTOFF_F) ? qfac : 0.0f;
            float sbh = sinf(0.5f * beta);
            float h = hav_lat + B * sbh * sbh;
            float r = 2.0f * asinf(fminf(sqrtf(fmaxf(h, 0.0f)), 1.0f));

            float xx = ca * cb * sg - sa * cg;
            float yy = sb * sg;
            float phi = atan2f(yy, xx);
            if (phi < 0.0f) phi += TWO_PI_F;

            float v[7];
            v[0] = fmaxf(0.0f, 1.0f - r * (1.0f / DR_F)) * mask;
            #pragma unroll
            for (int k = 1; k < 7; ++k) {
                int ir = (k - 1) / 3 + 1;
                int ip = (k - 1) % 3;
                float rad = fmaxf(0.0f, 1.0f - fabsf(r - (float)ir * DR_F) * (1.0f / DR_F));
                float dd  = fabsf(phi - (float)ip * DPH_F);
                dd = fminf(dd, TWO_PI_F - dd);
                float az = fmaxf(0.0f, 1.0f - dd * (1.0f / DPH_F));
                v[k] = rad * az * mask;
            }
            size_t b8 = ((size_t)(t * 21 + d) * 728 + s) * 8;
            #pragma unroll
            for (int k = 0; k < 7; ++k) g_psi8[b8 + k] = v[k];
            g_psi8[b8 + 7] = 0.0f;
            #pragma unroll
            for (int k = 0; k < 7; ++k) sums[k] += v[k];
        }
    }

    __shared__ float red[8][7];
    int lane = tid & 31, w = tid >> 5;
    #pragma unroll
    for (int k = 0; k < 7; ++k) {
        float s = sums[k];
        #pragma unroll
        for (int o = 16; o > 0; o >>= 1) s += __shfl_down_sync(0xffffffffu, s, o);
        if (lane == 0) red[w][k] = s;
    }
    __syncthreads();
    if (tid < 7) {
        float s = 0.0f;
        #pragma unroll
        for (int ww = 0; ww < 8; ++ww) s += red[ww][tid];
        g_sp[(tid * 361 + t) * 21 + d] = s;
    }
}

// ---------------- kernel INV ----------------
__global__ void inv_kernel() {
    int i = blockIdx.x * blockDim.x + threadIdx.x;
    if (i < 7 * 361) {
        float s = 0.0f;
        #pragma unroll
        for (int d = 0; d < 21; ++d) s += g_sp[i * 21 + d];
        g_invsc[i] = 1.0f / fmaxf(s, 1e-8f);
    }
}

// ---------------- kernel PACK ----------------
__global__ void pack_kernel(const float* __restrict__ wgt) {
    int idx = blockIdx.x * 256 + threadIdx.x;
    if (idx < 32 * 112) {
        int o = idx / 112;
        int j = idx - o * 112;
        int k = j >> 4;
        int h = j & 15;
        g_w2[idx * 2 + 0] = wgt[(o * CI + 2 * h) * KK + k];
        g_w2[idx * 2 + 1] = wgt[(o * CI + 2 * h + 1) * KK + k];
    }
    if (idx < 361) {
        #pragma unroll
        for (int k = 0; k < 7; ++k) g_invs2[idx * 8 + k] = g_invsc[k * 361 + idx];
        g_invs2[idx * 8 + 7] = 0.0f;
    }
}

// ---------------- kernel C: conv (direct LDG, no phase-1 smem) + fused GEMM ----------------
// smem only for phase 2: z2 float[112][64][2] = 57344B
#define SMEM_C (112 * 64 * 2 * 4)

#define PDUP(dst, v)     asm("mov.b64 %0,{%1,%1};" : "=l"(dst) : "f"(v))
#define CPAIR(dst, a, b) asm("mov.b64 %0,{%1,%2};" : "=l"(dst) : "f"(a), "f"(b))
#define UNP(lo, hi, v)   asm("mov.b64 {%0,%1},%2;" : "=f"(lo), "=f"(hi) : "l"(v))
#define F2(acc, p, x)    asm("fma.rn.f32x2 %0,%1,%2,%0;" : "+l"(acc) : "l"(p), "l"(x))
#define M2(acc, s)       asm("mul.rn.f32x2 %0,%0,%1;" : "+l"(acc) : "l"(s))

#define LOAD_X(S)                                                        \
    float4 x0 = __ldg(xr0 + (S));                                        \
    float4 x1 = __ldg(xr1 + (S));                                        \
    u64 c01, c23, c45, c67;                                              \
    CPAIR(c01, x0.x, x0.y); CPAIR(c23, x0.z, x0.w);                      \
    CPAIR(c45, x1.x, x1.y); CPAIR(c67, x1.z, x1.w);

#define SHELL2(S)                                                        \
    float k4s, k5s, k6s;                                                 \
    asm("ld.global.nc.v2.f32 {%0,%1},[%2];" : "=f"(k4s), "=f"(k5s)       \
        : "l"(pb + (size_t)(S) * 32 + 16));                              \
    asm("ld.global.nc.f32 %0,[%1];" : "=f"(k6s)                          \
        : "l"(pb + (size_t)(S) * 32 + 24));                              \
    u64 pk4, pk5, pk6; PDUP(pk4, k4s); PDUP(pk5, k5s); PDUP(pk6, k6s);   \
    F2(aK4[0], pk4, c01); F2(aK4[1], pk4, c23);                          \
    F2(aK4[2], pk4, c45); F2(aK4[3], pk4, c67);                          \
    F2(aK5[0], pk5, c01); F2(aK5[1], pk5, c23);                          \
    F2(aK5[2], pk5, c45); F2(aK5[3], pk5, c67);                          \
    F2(aK6[0], pk6, c01); F2(aK6[1], pk6, c23);                          \
    F2(aK6[2], pk6, c45); F2(aK6[3], pk6, c67);

#define BODY_OUT(S) { LOAD_X(S) SHELL2(S) }

#define BODY_IN(S) {                                                     \
    LOAD_X(S)                                                            \
    u64 p01, p23;                                                        \
    asm("ld.global.nc.v2.u64 {%0,%1},[%2];" : "=l"(p01), "=l"(p23)       \
        : "l"(pb + (size_t)(S) * 32));                                   \
    u64 du;                                                              \
    PDUP(du, x0.x); F2(a01[0], p01, du); F2(a23[0], p23, du);            \
    PDUP(du, x0.y); F2(a01[1], p01, du); F2(a23[1], p23, du);            \
    PDUP(du, x0.z); F2(a01[2], p01, du); F2(a23[2], p23, du);            \
    PDUP(du, x0.w); F2(a01[3], p01, du); F2(a23[3], p23, du);            \
    PDUP(du, x1.x); F2(a01[4], p01, du); F2(a23[4], p23, du);            \
    PDUP(du, x1.y); F2(a01[5], p01, du); F2(a23[5], p23, du);            \
    PDUP(du, x1.z); F2(a01[6], p01, du); F2(a23[6], p23, du);            \
    PDUP(du, x1.w); F2(a01[7], p01, du); F2(a23[7], p23, du);            \
    SHELL2(S) }

__global__ void __launch_bounds__(256, 2)
conv_kernel(float* __restrict__ y) {
    extern __shared__ float sm[];

    int ty = blockIdx.y;
    int t  = (ty & 1) ? (360 - (ty >> 1)) : (ty >> 1);  // heavy (polar) rows first
    int p0 = blockIdx.x * 64;
    int tid  = threadIdx.x;
    int lane = tid & 31;
    int wpi  = tid >> 5;
    int sub  = wpi & 1;                                 // p-subtile
    int cg   = wpi >> 1;                                // channel octet
    int qb   = 32 * sub + lane;

    u64 a01[8], a23[8], aK4[4], aK5[4], aK6[4];
    #pragma unroll
    for (int c = 0; c < 8; ++c) { a01[c] = 0ull; a23[c] = 0ull; }
    #pragma unroll
    for (int j = 0; j < 4; ++j) { aK4[j] = 0ull; aK5[j] = 0ull; aK6[j] = 0ull; }

    const float4* gx = (const float4*)g_xud;

    for (int d = 0; d < 21; ++d) {
        int lt = t + d - WOFF;
        if (lt < 0 || lt > 360) continue;
        int m = g_m[t * 21 + d];
        if (m < 0) continue;
        int m2 = g_m2[t * 21 + d];
        int cnt = 2 * m + 1;
        int base = p0 - m;
        base %= 720; if (base < 0) base += 720;
        int iA, iB;
        if (m2 < 0) { iA = cnt; iB = cnt; }
        else { iA = max(0, m - m2); iB = min(cnt, m + m2 + 1); }

        const float4* xr0 = gx + ((size_t)(2 * cg) * NLAT_O + lt) * XROW + base + qb;
        const float4* xr1 = xr0 + (size_t)NLAT_O * XROW;
        const char* pb = (const char*)g_psi8 + (size_t)(t * 21 + d) * (728 * 32);

        int s = 0;
        for (; s < iA; ++s) BODY_OUT(s)
        for (; s < iB; ++s) BODY_IN(s)
        for (; s < cnt; ++s) BODY_OUT(s)
    }

    // ---- fold 1/scale ----
    {
        const float* iv = g_invs2 + t * 8;
        u64 i01 = *(const u64*)(iv);
        u64 i23 = *(const u64*)(iv + 2);
        u64 d4, d5, d6;
        PDUP(d4, iv[4]); PDUP(d5, iv[5]); PDUP(d6, iv[6]);
        #pragma unroll
        for (int c = 0; c < 8; ++c) { M2(a01[c], i01); M2(a23[c], i23); }
        #pragma unroll
        for (int j = 0; j < 4; ++j) { M2(aK4[j], d4); M2(aK5[j], d5); M2(aK6[j], d6); }
    }

    // ---- phase 2: scatter z [112 kpair][64 p][2 par], GEMM ----
    float* z2f = sm;
    u64*   z2w = (u64*)sm;
    {
        #pragma unroll
        for (int c = 0; c < 8; ++c) {
            int i = 8 * cg + c;
            int half = i >> 1, par = i & 1;
            float lo, hi;
            UNP(lo, hi, a01[c]);
            z2f[(((0 * 16 + half) * 64 + qb) * 2) + par] = lo;
            z2f[(((1 * 16 + half) * 64 + qb) * 2) + par] = hi;
            UNP(lo, hi, a23[c]);
            z2f[(((2 * 16 + half) * 64 + qb) * 2) + par] = lo;
            z2f[(((3 * 16 + half) * 64 + qb) * 2) + par] = hi;
        }
        #pragma unroll
        for (int j = 0; j < 4; ++j) {
            int half = 4 * cg + j;
            z2w[(4 * 16 + half) * 64 + qb] = aK4[j];
            z2w[(5 * 16 + half) * 64 + qb] = aK5[j];
            z2w[(6 * 16 + half) * 64 + qb] = aK6[j];
        }
    }
    __syncthreads();

    // GEMM: thread = 2 adjacent p x 4 o
    int po2 = tid & 31;
    int og  = (tid >> 5) & 7;
    const ulonglong2* zp = (const ulonglong2*)z2f;
    const u64* wu = (const u64*)g_w2;

    u64 acc0[4], acc1[4];
    #pragma unroll
    for (int oo = 0; oo < 4; ++oo) { acc0[oo] = 0ull; acc1[oo] = 0ull; }

    for (int j = 0; j < 112; ++j) {
        ulonglong2 zv = zp[j * 32 + po2];
        #pragma unroll
        for (int oo = 0; oo < 4; ++oo) {
            u64 wv = __ldg(wu + (og + 8 * oo) * 112 + j);
            F2(acc0[oo], wv, zv.x);
            F2(acc1[oo], wv, zv.y);
        }
    }

    int pA0 = p0 + 2 * po2;
    int pA1 = pA0 + 1;
    #pragma unroll
    for (int oo = 0; oo < 4; ++oo) {
        int o = og + 8 * oo;
        float lo, hi;
        if (pA0 < 720) {
            UNP(lo, hi, acc0[oo]);
            y[((size_t)o * NLAT_O + t) * NLON_O + pA0] = lo + hi;
        }
        if (pA1 < 720) {
            UNP(lo, hi, acc1[oo]);
            y[((size_t)o * NLAT_O + t) * NLON_O + pA1] = lo + hi;
        }
    }
}

// ---------------- launcher ----------------
extern "C" void kernel_launch(void* const* d_in, const int* in_sizes, int n_in,
                              void* d_out, int out_size) {
    const float* x = (const float*)d_in[0];       // [1,32,240,480]
    const float* w = (const float*)d_in[1];       // [32,32,7]
    float* y = (float*)d_out;                     // [1,32,361,720]

    cudaFuncSetAttribute(conv_kernel, cudaFuncAttributeMaxDynamicSharedMemorySize, SMEM_C);

    int nA = CI * NLAT_O * NLON_O;
    upsample_kernel<<<(nA + 255) / 256, 256>>>(x);
    build_psi_kernel<<<dim3(21, 361), 256>>>();
    inv_kernel<<<(7 * 361 + 255) / 256, 256>>>();
    pack_kernel<<<(32 * 112 + 255) / 256, 256>>>(w);
    conv_kernel<<<dim3(12, 361), 256, SMEM_C>>>(y);
}